// round 3
// baseline (speedup 1.0000x reference)
#include <cuda_runtime.h>
#include <cuda_bf16.h>

// Label-smoothing KL loss, closed form:
//   per valid row r:  kl_r = c*log(c) + K*s*log(s) - c*lt - s*(S_r - lt [- lz])
// where S_r = sum_v log(max(x[r,v],eps)), lt = log(x[r,t]+eps),
// lz = log(x[r, V-100]+eps)  (JAX .at[-100] wraps), K = V-2 (V-1 if t==V-100).
// Targets are int32 on the wire (JAX x64 disabled).

#define LS_MAX_ROWS 65536

__device__ float g_row_contrib[LS_MAX_ROWS];
__device__ unsigned int g_done_count = 0;

// Fast natural log for normal positive floats (>= 1e-12, no subnormals).
// Mantissa reduced to [2/3, 4/3), degree-7 Taylor of ln(1+f), |abs err| < 2e-5.
__device__ __forceinline__ float fast_log(float v) {
    int i = __float_as_int(v);
    int e = (i - 0x3f2aaaab) & 0xff800000;
    float m = __int_as_float(i - e);
    float f = m - 1.0f;
    float p = fmaf(0.142857143f, f, -0.166666667f);
    p = fmaf(p, f, 0.20f);
    p = fmaf(p, f, -0.25f);
    p = fmaf(p, f, 0.333333333f);
    p = fmaf(p, f, -0.5f);
    p = fmaf(p, f, 1.0f);
    return fmaf((float)(e >> 23), 0.693147180559945f, p * f);
}

// Accumulate ln(max(x,1e-12)) split into poly part (fma pipe) + exponent (alu pipe).
__device__ __forceinline__ void accum(float x, float& psum, int& esum) {
    float v = fmaxf(x, 1e-12f);           // FMNMX: alu pipe, not fma
    int i = __float_as_int(v);
    int e = (i - 0x3f2aaaab) & 0xff800000;
    float m = __int_as_float(i - e);
    esum += (e >> 23);
    float f = m - 1.0f;
    float p = fmaf(0.142857143f, f, -0.166666667f);
    p = fmaf(p, f, 0.20f);
    p = fmaf(p, f, -0.25f);
    p = fmaf(p, f, 0.333333333f);
    p = fmaf(p, f, -0.5f);
    p = fmaf(p, f, 1.0f);
    psum = fmaf(p, f, psum);
}

template <int BLOCK>
__global__ void __launch_bounds__(BLOCK)
ls_row_kernel(const float* __restrict__ x,
              const int* __restrict__ tgt,
              int V, int N, float* __restrict__ out) {
    const int row = blockIdx.x;
    const float* __restrict__ px = x + (size_t)row * (size_t)V;

    // 16B-alignment prologue: row bases are only 4B-aligned (V odd).
    const int mis = (int)(((unsigned long long)(size_t)px) & 15ull);  // 0,4,8,12
    const int pre = (mis == 0) ? 0 : ((16 - mis) >> 2);               // 0..3

    float ps0 = 0.0f, ps1 = 0.0f, ps2 = 0.0f, ps3 = 0.0f;
    int es = 0;

    if (threadIdx.x < pre)
        accum(__ldg(px + threadIdx.x), ps0, es);

    // Aligned float4 body
    const float4* __restrict__ px4 = (const float4*)(px + pre);
    const int n4 = (V - pre) >> 2;
    #pragma unroll 2
    for (int j = threadIdx.x; j < n4; j += BLOCK) {
        float4 q = __ldg(px4 + j);
        accum(q.x, ps0, es);
        accum(q.y, ps1, es);
        accum(q.z, ps2, es);
        accum(q.w, ps3, es);
    }

    // Scalar tail
    const int tail = pre + (n4 << 2);
    const int jt = tail + threadIdx.x;
    if (jt < V)
        accum(__ldg(px + jt), ps1, es);

    float psum = (ps0 + ps1) + (ps2 + ps3);

    // Warp reduce
    #pragma unroll
    for (int o = 16; o > 0; o >>= 1) {
        psum += __shfl_down_sync(0xffffffffu, psum, o);
        es   += __shfl_down_sync(0xffffffffu, es, o);
    }

    constexpr int NW = BLOCK / 32;
    __shared__ float sf[NW];
    __shared__ int   se[NW];
    const int lane = threadIdx.x & 31;
    const int wid  = threadIdx.x >> 5;
    if (lane == 0) { sf[wid] = psum; se[wid] = es; }
    __syncthreads();

    if (threadIdx.x == 0) {
        float pt = 0.0f;
        int   et = 0;
        #pragma unroll
        for (int w = 0; w < NW; w++) { pt += sf[w]; et += se[w]; }

        float S = fmaf((float)et, 0.693147180559945f, pt);  // S_r

        int t = tgt[row];
        float contrib = 0.0f;
        if (t != -100 && t >= 0 && t < V) {
            const int zidx = V - 100;
            const float c = 0.9f;
            const float logc = -0.105360515657826f;         // ln(0.9)
            const float s = 0.1f / (float)(V - 1);
            const float logs = fast_log(s);

            float lt = fast_log(__ldg(px + t) + 1e-12f);
            if (t == zidx) {
                contrib = c * logc + (float)(V - 1) * s * logs
                        - c * lt - s * (S - lt);
            } else {
                float lz = fast_log(__ldg(px + zidx) + 1e-12f);
                contrib = c * logc + (float)(V - 2) * s * logs
                        - c * lt - s * (S - lt - lz);
            }
        }
        g_row_contrib[row] = contrib;
    }

    // Last-block final reduction (deterministic: one block, fixed order).
    __shared__ bool is_last;
    if (threadIdx.x == 0) {
        __threadfence();
        unsigned int prev = atomicAdd(&g_done_count, 1u);
        is_last = (prev == (unsigned int)(gridDim.x - 1));
    }
    __syncthreads();

    if (is_last) {
        float s = 0.0f;
        for (int i = threadIdx.x; i < N; i += BLOCK)
            s += g_row_contrib[i];

        #pragma unroll
        for (int o = 16; o > 0; o >>= 1)
            s += __shfl_down_sync(0xffffffffu, s, o);

        __shared__ float sw[NW];
        if (lane == 0) sw[wid] = s;
        __syncthreads();
        if (threadIdx.x == 0) {
            float v = 0.0f;
            #pragma unroll
            for (int w = 0; w < NW; w++) v += sw[w];
            out[0] = v;
            g_done_count = 0;   // reset for next graph replay
        }
    }
}

extern "C" void kernel_launch(void* const* d_in, const int* in_sizes, int n_in,
                              void* d_out, int out_size) {
    const float* x = (const float*)d_in[0];
    const int* tgt = (const int*)d_in[1];
    const int N = in_sizes[1];
    const int V = in_sizes[0] / N;

    int rows = N > LS_MAX_ROWS ? LS_MAX_ROWS : N;
    ls_row_kernel<256><<<rows, 256>>>(x, tgt, V, rows, (float*)d_out);
}